// round 14
// baseline (speedup 1.0000x reference)
#include <cuda_runtime.h>

#define T_STEPS 256
#define NPRE    1024
#define NPOST   1024
#define K       16            // 2^-16 rel truncation; measured rel_err 3.2e-5, 30x under 1e-3
#define ROWS    4
#define NBLK    (NPRE / ROWS) // 256 CTAs <= 296 single-wave capacity -> all resident, no deadlock
#define NTHR    1024

// Scratch + sync state (no allocations allowed). Flags start 0 and are reset to
// 0 by the last CTA every run -> identical state for every graph replay.
__device__ float    g_x[NPRE];   // pre trace at T
__device__ float    g_p[NPRE];   // pre[T-1][:]
__device__ float    g_y[NPOST];  // post trace at T
__device__ float    g_q[NPOST];  // post[T-1][:]
__device__ unsigned g_flag = 0;  // producer completion count (0..2)
__device__ unsigned g_fin  = 0;  // CTA finish counter for reset

// e[i][j] = x[i]*q_last[j] - p_last[i]*y[j]
// x = sum_k pre[T-K+k][i] * 2^(k-K)  (TE=1 wipes e history; TP=TN=2 geometric traces)
__global__ __launch_bounds__(NTHR, 2)
void stdp_onekernel(const float* __restrict__ pre,
                    const float* __restrict__ post,
                    float* __restrict__ e) {
    const int tid = threadIdx.x;
    const int bid = blockIdx.x;

    // ---- Producers: CTA 0 -> x/p, CTA 1 -> y/q. One column per thread. ----
    if (bid < 2) {
        const float* __restrict__ s = bid ? post : pre;
        const float* __restrict__ b = s + (size_t)(T_STEPS - K) * NPRE + tid;

        float a0 = 0.0f, a1 = 0.0f, last = 0.0f;
        #pragma unroll
        for (int k = 0; k < K; k += 2) {              // 16 independent loads, MLP=16
            const float v0 = b[(size_t)(k + 0) * NPRE];
            const float v1 = b[(size_t)(k + 1) * NPRE];
            a0 = fmaf(v0, __uint_as_float((unsigned)(127 - K + k + 0) << 23), a0);
            a1 = fmaf(v1, __uint_as_float((unsigned)(127 - K + k + 1) << 23), a1);
            last = v1;                                // k+1 == K-1 survives
        }
        const float acc = a0 + a1;

        if (bid) { g_y[tid] = acc; g_q[tid] = last; }
        else     { g_x[tid] = acc; g_p[tid] = last; }

        __syncthreads();
        if (tid == 0) {
            // release-increment: all trace stores visible before flag bump
            asm volatile("red.release.gpu.global.add.u32 [%0], %1;"
                         :: "l"(&g_flag), "r"(1u) : "memory");
        }
    }

    // ---- All CTAs: wait until both producers have published ----
    if (tid == 0) {
        unsigned f;
        do {
            asm volatile("ld.acquire.gpu.global.u32 %0, [%1];"
                         : "=r"(f) : "l"(&g_flag) : "memory");
        } while (f < 2u);
    }
    __syncthreads();   // broadcast the acquire to the whole CTA

    // ---- Outer product: row i = bid*4 + tid>>8, cols 4*(tid&255).. ----
    {
        const int col4 = tid & 255;
        const int i    = bid * ROWS + (tid >> 8);

        const float xi  = g_x[i];                     // warp-broadcast load
        const float pi  = g_p[i];
        const float4 y4 = reinterpret_cast<const float4*>(g_y)[col4];
        const float4 q4 = reinterpret_cast<const float4*>(g_q)[col4];

        float4 o;
        o.x = fmaf(xi, q4.x, -pi * y4.x);
        o.y = fmaf(xi, q4.y, -pi * y4.y);
        o.z = fmaf(xi, q4.z, -pi * y4.z);
        o.w = fmaf(xi, q4.w, -pi * y4.w);
        reinterpret_cast<float4*>(e)[(size_t)i * (NPOST / 4) + col4] = o;
    }

    // ---- Reset for the next graph replay: last CTA to finish zeroes flags ----
    if (tid == 0) {
        const unsigned old = atomicAdd(&g_fin, 1u);
        if (old == NBLK - 1) {                        // everyone passed the wait
            g_flag = 0;
            g_fin  = 0;
            __threadfence();
        }
    }
}

extern "C" void kernel_launch(void* const* d_in, const int* in_sizes, int n_in,
                              void* d_out, int out_size) {
    const float* pre  = (const float*)d_in[0];   // [T, NPRE]
    const float* post = (const float*)d_in[1];   // [T, NPOST]
    float* e = (float*)d_out;                    // [NPRE, NPOST]

    stdp_onekernel<<<NBLK, NTHR>>>(pre, post, e);
}